// round 9
// baseline (speedup 1.0000x reference)
#include <cuda_runtime.h>
#include <math.h>

#define B_ 16
#define N_ 1000
#define H_ 128
#define M_ 2
#define T_ 16
#define NCH 16
#define CHUNK 63
#define NEGBIG 1e8f
#define PROJ_SZ (B_*M_*N_*H_)

__device__ __align__(256) float g_PROJ[6 * PROJ_SZ]; // r1,v1,r3,v3,r4,v4
__device__ __align__(256) float g_R2[B_ * N_ * H_];
__device__ __align__(256) float g_WC[5 * 2 * H_ * H_]; // Wmh@Wq3(m0,m1), Wmh@Wq4(m0,m1), Wmh@Wq2
__device__ __align__(256) float g_HMEAN[B_ * H_];
__device__ __align__(256) float g_MASK[B_ * N_];
__device__ __align__(256) float g_Q[B_ * M_ * H_];
__device__ __align__(256) float g_QP[B_ * H_];
__device__ __align__(256) float g_U[B_ * N_];
__device__ __align__(256) float g_PM[B_ * M_ * NCH];
__device__ __align__(256) float g_PZ[B_ * M_ * NCH];
__device__ __align__(256) float g_PG[B_ * M_ * NCH * H_];
__device__ __align__(256) float g_PBV[B_ * NCH];
__device__ __align__(256) int   g_PBI[B_ * NCH];
__device__ int g_CNT[B_];
__device__ int g_CNT2[B_];

__device__ __forceinline__ float fast_tanh(float x) {
    // 1 - 2/(exp(2x)+1): exact at both saturations, abs err ~1e-7 via __expf
    float e = __expf(2.0f * x);
    return 1.0f - __fdividef(2.0f, e + 1.0f);
}

// ---------------- mean over N ----------------------------------------------
__global__ void __launch_bounds__(H_) mean_kernel(const float* __restrict__ enc) {
    int b = blockIdx.x, h = threadIdx.x;
    const float* p = enc + (size_t)b * N_ * H_ + h;
    float a0 = 0.f, a1 = 0.f, a2 = 0.f, a3 = 0.f;
    for (int n = 0; n < N_; n += 4) {
        a0 += p[(size_t)(n + 0) * H_]; a1 += p[(size_t)(n + 1) * H_];
        a2 += p[(size_t)(n + 2) * H_]; a3 += p[(size_t)(n + 3) * H_];
    }
    g_HMEAN[b * H_ + h] = (a0 + a1 + a2 + a3) * (1.0f / N_);
}

// ---------------- precompute GEMMs: 13 jobs [16000,128]x[128,128] ----------
#define GEMM_SMEM ((128 * 68 + 128 * 128) * 4)
__global__ void __launch_bounds__(256, 2) gemm_kernel(
    const float* __restrict__ enc,
    const float* __restrict__ Wr1, const float* __restrict__ V1,
    const float* __restrict__ Wr3, const float* __restrict__ V3,
    const float* __restrict__ Wr4, const float* __restrict__ V4,
    const float* __restrict__ Wr2)
{
    extern __shared__ float sm[];
    float* As = sm;              // [k=128][r pitch 68], valid r<64
    float* Bs = sm + 128 * 68;   // [k=128][h=128]
    int tile = blockIdx.x, job = blockIdx.y, tid = threadIdx.x;

    const float* W; float* dst; int m = 0; int isR2 = (job == 12);
    if (isR2) { W = Wr2; dst = g_R2; }
    else {
        int fam = job >> 1; m = job & 1;
        switch (fam) {
            case 0: W = Wr1; break; case 1: W = V1; break;
            case 2: W = Wr3; break; case 3: W = V3; break;
            case 4: W = Wr4; break; default: W = V4; break;
        }
        W += m * H_ * H_;
        dst = g_PROJ + (size_t)fam * PROJ_SZ;
    }
    int row0 = tile * 64;

    // A tile: coalesced GMEM (4 rows x 8 float4 per warp), 4-way STS banks
    #pragma unroll
    for (int ch = 0; ch < 8; ch++) {
        int e = ch * 256 + tid;            // 0..2047
        int r  = (e >> 3) & 63;
        int kq = (e & 7) | ((e >> 9) << 3);
        float4 a = *(const float4*)&enc[(size_t)(row0 + r) * H_ + kq * 4];
        As[(kq * 4 + 0) * 68 + r] = a.x;
        As[(kq * 4 + 1) * 68 + r] = a.y;
        As[(kq * 4 + 2) * 68 + r] = a.z;
        As[(kq * 4 + 3) * 68 + r] = a.w;
    }
    #pragma unroll
    for (int ch = 0; ch < 16; ch++) {
        int e = ch * 256 + tid;
        ((float4*)Bs)[e] = ((const float4*)W)[e];
    }
    __syncthreads();

    int rg = tid >> 5, cg = tid & 31;
    float acc[8][4];
    #pragma unroll
    for (int i = 0; i < 8; i++) { acc[i][0]=acc[i][1]=acc[i][2]=acc[i][3]=0.f; }

    #pragma unroll 4
    for (int k = 0; k < 128; k++) {
        float4 A0 = *(const float4*)(As + k * 68 + rg * 8);
        float4 A1 = *(const float4*)(As + k * 68 + rg * 8 + 4);
        float4 Bv = *(const float4*)(Bs + k * 128 + cg * 4);
        float a[8] = {A0.x, A0.y, A0.z, A0.w, A1.x, A1.y, A1.z, A1.w};
        #pragma unroll
        for (int i = 0; i < 8; i++) {
            acc[i][0] = fmaf(a[i], Bv.x, acc[i][0]);
            acc[i][1] = fmaf(a[i], Bv.y, acc[i][1]);
            acc[i][2] = fmaf(a[i], Bv.z, acc[i][2]);
            acc[i][3] = fmaf(a[i], Bv.w, acc[i][3]);
        }
    }
    #pragma unroll
    for (int i = 0; i < 8; i++) {
        int row = row0 + rg * 8 + i;
        size_t off;
        if (isR2) off = (size_t)row * H_;
        else { int bb = row / N_, n = row - bb * N_;
               off = (size_t)((bb * M_ + m) * N_ + n) * H_; }
        float4 o = make_float4(acc[i][0], acc[i][1], acc[i][2], acc[i][3]);
        *(float4*)&dst[off + cg * 4] = o;
    }
}

// ---------------- combined merge weights: g_WC = Wmh @ Wq_next -------------
// jobs: 0,1 = Wmh@Wq3[m]; 2,3 = Wmh@Wq4[m]; 4 = Wmh@Wq2
__global__ void __launch_bounds__(256) combo_kernel(
    const float* __restrict__ Wmh, const float* __restrict__ Wq3,
    const float* __restrict__ Wq4, const float* __restrict__ Wq2)
{
    int rt = blockIdx.x, job = blockIdx.y, tid = threadIdx.x;
    const float* Wq = (job < 2) ? Wq3 + job * H_ * H_
                    : (job < 4) ? Wq4 + (job - 2) * H_ * H_ : Wq2;
    __shared__ float As[16][H_];           // 16 rows of Wmh
    for (int e = tid; e < 16 * H_; e += 256)
        As[e >> 7][e & 127] = Wmh[(size_t)(rt * 16 + (e >> 7)) * H_ + (e & 127)];
    __syncthreads();
    int c = tid & 127, r0 = (tid >> 7) * 8;
    float acc[8] = {0.f,0.f,0.f,0.f,0.f,0.f,0.f,0.f};
    #pragma unroll 4
    for (int k = 0; k < H_; k++) {
        float w = Wq[(size_t)k * H_ + c];
        #pragma unroll
        for (int i = 0; i < 8; i++) acc[i] = fmaf(As[r0 + i][k], w, acc[i]);
    }
    #pragma unroll
    for (int i = 0; i < 8; i++)
        g_WC[(size_t)(job * 256 + rt * 16 + r0 + i) * H_ + c] = acc[i];
}

// ---------------- init ------------------------------------------------------
__global__ void __launch_bounds__(256) init_kernel(
    const float* __restrict__ mask0, const float* __restrict__ dec,
    const float* __restrict__ Wq1)
{
    int b = blockIdx.x, tid = threadIdx.x;
    for (int n = tid; n < N_; n += 256) g_MASK[b * N_ + n] = mask0[b * N_ + n];
    if (b == 0 && tid < B_) { g_CNT[tid] = 0; g_CNT2[tid] = 0; }
    __shared__ float q0[2 * H_];
    if (tid < H_) { q0[tid] = g_HMEAN[b * H_ + tid]; q0[H_ + tid] = dec[tid]; }
    __syncthreads();
    int mm = tid >> 7, h = tid & 127;
    const float* Wp = Wq1 + (size_t)mm * 2 * H_ * H_ + h;
    float a = 0.f;
    #pragma unroll 16
    for (int i = 0; i < 2 * H_; i++) a = fmaf(q0[i], Wp[(size_t)i * H_], a);
    g_Q[(b * M_ + mm) * H_ + h] = a;
}

// ---------------- fused glimpse --------------------------------------------
// grid (NCH, M, B), 256 threads. Two n per iteration so the two shfl-reduce
// chains overlap. Last-arriving block per b merges chunks and projects the
// next query through g_WC (or writes g_QP when isPtr).
__global__ void __launch_bounds__(256) glimpse_kernel(int slot, int combo, int isPtr)
{
    int c = blockIdx.x, m = blockIdx.y, b = blockIdx.z;
    int tid = threadIdx.x, w = tid >> 5, l = tid & 31;
    const float* rBase = g_PROJ + (size_t)slot * PROJ_SZ + (size_t)(b * M_ + m) * N_ * H_;
    const float* vBase = g_PROJ + (size_t)(slot + 1) * PROJ_SZ + (size_t)(b * M_ + m) * N_ * H_;
    float4 q4 = *(const float4*)&g_Q[(b * M_ + m) * H_ + 4 * l];

    float mloc = -INFINITY, Z = 0.f;
    float4 G = make_float4(0.f, 0.f, 0.f, 0.f);
    int n0 = c * CHUNK, nEnd = min(n0 + CHUNK, N_);
    for (int n = n0 + w; n < nEnd; n += 16) {
        int n2 = n + 8;
        bool has2 = (n2 < nEnd);                     // warp-uniform
        float4 r4 = *(const float4*)&rBase[(size_t)n * H_ + 4 * l];
        float4 v4 = *(const float4*)&vBase[(size_t)n * H_ + 4 * l];
        float sp0 = fast_tanh(q4.x + r4.x) * v4.x;
        sp0 = fmaf(fast_tanh(q4.y + r4.y), v4.y, sp0);
        sp0 = fmaf(fast_tanh(q4.z + r4.z), v4.z, sp0);
        sp0 = fmaf(fast_tanh(q4.w + r4.w), v4.w, sp0);
        float4 r4b = make_float4(0.f, 0.f, 0.f, 0.f);
        float sp1 = 0.f;
        if (has2) {
            r4b = *(const float4*)&rBase[(size_t)n2 * H_ + 4 * l];
            float4 v4b = *(const float4*)&vBase[(size_t)n2 * H_ + 4 * l];
            sp1 = fast_tanh(q4.x + r4b.x) * v4b.x;
            sp1 = fmaf(fast_tanh(q4.y + r4b.y), v4b.y, sp1);
            sp1 = fmaf(fast_tanh(q4.z + r4b.z), v4b.z, sp1);
            sp1 = fmaf(fast_tanh(q4.w + r4b.w), v4b.w, sp1);
        }
        #pragma unroll
        for (int o = 16; o; o >>= 1) {               // two independent chains
            sp0 += __shfl_xor_sync(0xffffffffu, sp0, o);
            sp1 += __shfl_xor_sync(0xffffffffu, sp1, o);
        }
        float s0 = fmaf(-NEGBIG, g_MASK[b * N_ + n], 10.0f * fast_tanh(sp0));
        float mn = fmaxf(mloc, s0);
        float s1 = 0.f;
        if (has2) {
            s1 = fmaf(-NEGBIG, g_MASK[b * N_ + n2], 10.0f * fast_tanh(sp1));
            mn = fmaxf(mn, s1);
        }
        float sc = __expf(mloc - mn);
        float p0 = __expf(s0 - mn);
        float p1 = has2 ? __expf(s1 - mn) : 0.f;
        Z = fmaf(Z, sc, p0 + p1);
        G.x = fmaf(p0, r4.x, fmaf(p1, r4b.x, G.x * sc));
        G.y = fmaf(p0, r4.y, fmaf(p1, r4b.y, G.y * sc));
        G.z = fmaf(p0, r4.z, fmaf(p1, r4b.z, G.z * sc));
        G.w = fmaf(p0, r4.w, fmaf(p1, r4b.w, G.w * sc));
        mloc = mn;
    }

    __shared__ float sM[8], sZ[8];
    __shared__ __align__(16) float sG[8 * H_];
    if (l == 0) { sM[w] = mloc; sZ[w] = Z; }
    *(float4*)&sG[w * H_ + 4 * l] = G;
    __syncthreads();
    if (tid < H_) {
        float M8 = sM[0];
        #pragma unroll
        for (int ww = 1; ww < 8; ww++) M8 = fmaxf(M8, sM[ww]);
        float acc = 0.f, zz = 0.f;
        #pragma unroll
        for (int ww = 0; ww < 8; ww++) {
            float e = __expf(sM[ww] - M8);
            acc = fmaf(sG[ww * H_ + tid], e, acc);
            zz  = fmaf(sZ[ww], e, zz);
        }
        g_PG[((b * M_ + m) * NCH + c) * H_ + tid] = acc;
        if (tid == 0) { g_PM[(b * M_ + m) * NCH + c] = M8;
                        g_PZ[(b * M_ + m) * NCH + c] = zz; }
    }
    // release: writes -> fence -> sync -> counter
    __threadfence();
    __syncthreads();
    __shared__ int lastFlag;
    if (tid == 0) lastFlag = (atomicAdd(&g_CNT[b], 1) == M_ * NCH - 1);
    __syncthreads();
    if (!lastFlag) return;
    __threadfence();

    __shared__ float gflat[M_ * H_];
    int mm = tid >> 7, h = tid & 127;
    {
        const float* PMp = &g_PM[(b * M_ + mm) * NCH];
        const float* PZp = &g_PZ[(b * M_ + mm) * NCH];
        const float* PGp = &g_PG[(size_t)((b * M_ + mm) * NCH) * H_ + h];
        float Mx = -INFINITY;
        #pragma unroll
        for (int cc = 0; cc < NCH; cc++) Mx = fmaxf(Mx, PMp[cc]);
        float Zm = 0.f, Gv = 0.f;
        #pragma unroll
        for (int cc = 0; cc < NCH; cc++) {
            float e = __expf(PMp[cc] - Mx);
            Zm = fmaf(PZp[cc], e, Zm);
            Gv = fmaf(PGp[(size_t)cc * H_], e, Gv);
        }
        gflat[mm * H_ + h] = __fdividef(Gv, Zm);
    }
    __syncthreads();
    if (isPtr) {
        __shared__ float qpart[2][H_];
        const float* Wp = g_WC + (size_t)(4 * 256 + mm * 128) * H_ + h;
        const float* gp = gflat + mm * 128;
        float a = 0.f;
        #pragma unroll 16
        for (int i = 0; i < 128; i++) a = fmaf(gp[i], Wp[(size_t)i * H_], a);
        qpart[mm][h] = a;
        __syncthreads();
        if (tid < H_) g_QP[b * H_ + tid] = qpart[0][tid] + qpart[1][tid];
    } else {
        const float* Wp = g_WC + (size_t)(combo + mm) * 256 * H_ + h;
        float a = 0.f;
        #pragma unroll 16
        for (int i = 0; i < 256; i++) a = fmaf(gflat[i], Wp[(size_t)i * H_], a);
        g_Q[(b * M_ + mm) * H_ + h] = a;
    }
    if (tid == 0) g_CNT[b] = 0;
}

// ---------------- fused pointer step ---------------------------------------
__global__ void __launch_bounds__(256) pointer_kernel(
    int t, const float* __restrict__ enc, const float* __restrict__ Wq1,
    const float* __restrict__ Vec2, float* __restrict__ out)
{
    int c = blockIdx.x, b = blockIdx.y;
    int tid = threadIdx.x, w = tid >> 5, l = tid & 31;
    float4 qp4 = *(const float4*)&g_QP[b * H_ + 4 * l];
    float4 v2  = *(const float4*)&Vec2[4 * l];

    float bestv = -INFINITY; int besti = 0;
    int n0 = c * CHUNK, nEnd = min(n0 + CHUNK, N_);
    for (int n = n0 + w; n < nEnd; n += 16) {
        int n2 = n + 8;
        bool has2 = (n2 < nEnd);
        float4 r4 = *(const float4*)&g_R2[(size_t)(b * N_ + n) * H_ + 4 * l];
        float sp0 = fast_tanh(qp4.x + r4.x) * v2.x;
        sp0 = fmaf(fast_tanh(qp4.y + r4.y), v2.y, sp0);
        sp0 = fmaf(fast_tanh(qp4.z + r4.z), v2.z, sp0);
        sp0 = fmaf(fast_tanh(qp4.w + r4.w), v2.w, sp0);
        float sp1 = 0.f;
        if (has2) {
            float4 r4b = *(const float4*)&g_R2[(size_t)(b * N_ + n2) * H_ + 4 * l];
            sp1 = fast_tanh(qp4.x + r4b.x) * v2.x;
            sp1 = fmaf(fast_tanh(qp4.y + r4b.y), v2.y, sp1);
            sp1 = fmaf(fast_tanh(qp4.z + r4b.z), v2.z, sp1);
            sp1 = fmaf(fast_tanh(qp4.w + r4b.w), v2.w, sp1);
        }
        #pragma unroll
        for (int o = 16; o; o >>= 1) {
            sp0 += __shfl_xor_sync(0xffffffffu, sp0, o);
            sp1 += __shfl_xor_sync(0xffffffffu, sp1, o);
        }
        float u0 = fmaf(-NEGBIG, g_MASK[b * N_ + n], 10.0f * fast_tanh(sp0));
        if (l == 0) g_U[b * N_ + n] = u0;
        if (u0 > bestv) { bestv = u0; besti = n; }   // increasing n: first-max wins
        if (has2) {
            float u1 = fmaf(-NEGBIG, g_MASK[b * N_ + n2], 10.0f * fast_tanh(sp1));
            if (l == 0) g_U[b * N_ + n2] = u1;
            if (u1 > bestv) { bestv = u1; besti = n2; }
        }
    }
    __shared__ float bv[8]; __shared__ int bi[8];
    if (l == 0) { bv[w] = bestv; bi[w] = besti; }
    __syncthreads();
    if (tid == 0) {
        float v = bv[0]; int i = bi[0];
        #pragma unroll
        for (int ww = 1; ww < 8; ww++)
            if (bv[ww] > v || (bv[ww] == v && bi[ww] < i)) { v = bv[ww]; i = bi[ww]; }
        g_PBV[b * NCH + c] = v; g_PBI[b * NCH + c] = i;
    }
    __threadfence();
    __syncthreads();
    __shared__ int lastFlag;
    if (tid == 0) lastFlag = (atomicAdd(&g_CNT2[b], 1) == NCH - 1);
    __syncthreads();
    if (!lastFlag) return;
    __threadfence();

    __shared__ float mxS; __shared__ int selS; __shared__ float red[256];
    if (tid == 0) {
        float v = g_PBV[b * NCH]; int i = g_PBI[b * NCH];
        #pragma unroll
        for (int cc = 1; cc < NCH; cc++) {
            float vv = g_PBV[b * NCH + cc]; int ii = g_PBI[b * NCH + cc];
            if (vv > v || (vv == v && ii < i)) { v = vv; i = ii; }
        }
        mxS = v; selS = i;
    }
    __syncthreads();
    float mx = mxS;
    float acc = 0.f;
    for (int n = tid; n < N_; n += 256) acc += __expf(g_U[b * N_ + n] - mx);
    red[tid] = acc;
    __syncthreads();
    #pragma unroll
    for (int st = 128; st; st >>= 1) {
        if (tid < st) red[tid] += red[tid + st];
        __syncthreads();
    }
    float logZ = logf(red[0]);
    float* outp = out + ((size_t)t * B_ + b) * N_;
    for (int n = tid; n < N_; n += 256)
        outp[n] = g_U[b * N_ + n] - mx - logZ;

    int sel = selS;
    if (tid == 0) {
        g_MASK[b * N_ + sel] = 1.0f;
        out[(size_t)T_ * B_ * N_ + (size_t)t * B_ + b] = (float)sel;
        g_CNT2[b] = 0;
    }
    // next-step query: q0 = [h_mean, enc[b,sel,:]] through Wq1
    __shared__ float q0[2 * H_];
    if (tid < H_) {
        q0[tid] = g_HMEAN[b * H_ + tid];
        q0[H_ + tid] = enc[((size_t)b * N_ + sel) * H_ + tid];
    }
    __syncthreads();
    int mm = tid >> 7, h = tid & 127;
    const float* Wp = Wq1 + (size_t)mm * 2 * H_ * H_ + h;
    float a = 0.f;
    #pragma unroll 16
    for (int i = 0; i < 2 * H_; i++) a = fmaf(q0[i], Wp[(size_t)i * H_], a);
    g_Q[(b * M_ + mm) * H_ + h] = a;
}

// ---------------- launch ----------------------------------------------------
extern "C" void kernel_launch(void* const* d_in, const int* in_sizes, int n_in,
                              void* d_out, int out_size) {
    const float* enc   = (const float*)d_in[0];
    const float* mask0 = (const float*)d_in[1];
    const float* Wq1   = (const float*)d_in[2];
    const float* Wref1 = (const float*)d_in[3];
    const float* Vec1  = (const float*)d_in[4];
    const float* Wq3   = (const float*)d_in[5];
    const float* Wref3 = (const float*)d_in[6];
    const float* Vec3  = (const float*)d_in[7];
    const float* Wq4   = (const float*)d_in[8];
    const float* Wref4 = (const float*)d_in[9];
    const float* Vec4  = (const float*)d_in[10];
    const float* Wmh   = (const float*)d_in[11];
    const float* Wq2   = (const float*)d_in[12];
    const float* Wref2 = (const float*)d_in[13];
    const float* Vec2  = (const float*)d_in[14];
    const float* dec   = (const float*)d_in[15];
    float* out = (float*)d_out;

    cudaFuncSetAttribute(gemm_kernel,
        cudaFuncAttributeMaxDynamicSharedMemorySize, GEMM_SMEM);

    mean_kernel<<<B_, H_>>>(enc);
    dim3 gg(250, 13);
    gemm_kernel<<<gg, 256, GEMM_SMEM>>>(enc, Wref1, Vec1, Wref3, Vec3,
                                        Wref4, Vec4, Wref2);
    dim3 gc(16, 5);
    combo_kernel<<<gc, 256>>>(Wmh, Wq3, Wq4, Wq2);
    init_kernel<<<B_, 256>>>(mask0, dec, Wq1);

    dim3 gl(NCH, M_, B_);
    dim3 gp(NCH, B_);
    for (int t = 0; t < T_; t++) {
        glimpse_kernel<<<gl, 256>>>(0, 0, 0);
        glimpse_kernel<<<gl, 256>>>(2, 2, 0);
        glimpse_kernel<<<gl, 256>>>(4, 4, 1);
        pointer_kernel<<<gp, 256>>>(t, enc, Wq1, Vec2, out);
    }
}